// round 13
// baseline (speedup 1.0000x reference)
#include <cuda_runtime.h>
#include <cuda_fp16.h>

#define NN 200000
#define EE 3200000

// ---- device scratch (no runtime allocation allowed) ----
__device__ int      g_is64;
__device__ int      g_cnt_src[NN];
__device__ int      g_cnt_dst[NN];
__device__ int      g_fill[NN];
__device__ int      g_rowptr[NN];
__device__ float    g_dinv[NN];
__device__ unsigned g_cursor;
__device__ int2     g_pairs[EE];       // (src, w-bits) grouped contiguously by dst
__device__ uint4    g_hh [NN * 4];     // fp16 features: H / residual
__device__ uint4    g_ah [NN * 4];     // fp16 features: A (intermediate)
__device__ uint4    g_t1h[NN * 4];     // fp16 features: T1

// ---------------------------------------------------------------- helpers

__device__ __forceinline__ uint4 pack_h8(float4 a, float4 b) {
    __half2 p0 = __floats2half2_rn(a.x, a.y);
    __half2 p1 = __floats2half2_rn(a.z, a.w);
    __half2 p2 = __floats2half2_rn(b.x, b.y);
    __half2 p3 = __floats2half2_rn(b.z, b.w);
    uint4 r;
    r.x = *reinterpret_cast<unsigned*>(&p0);
    r.y = *reinterpret_cast<unsigned*>(&p1);
    r.z = *reinterpret_cast<unsigned*>(&p2);
    r.w = *reinterpret_cast<unsigned*>(&p3);
    return r;
}

__device__ __forceinline__ void unpack_h8(uint4 u, float4& a, float4& b) {
    float2 f0 = __half22float2(*reinterpret_cast<__half2*>(&u.x));
    float2 f1 = __half22float2(*reinterpret_cast<__half2*>(&u.y));
    float2 f2 = __half22float2(*reinterpret_cast<__half2*>(&u.z));
    float2 f3 = __half22float2(*reinterpret_cast<__half2*>(&u.w));
    a = make_float4(f0.x, f0.y, f1.x, f1.y);
    b = make_float4(f2.x, f2.y, f3.x, f3.y);
}

// ---------------------------------------------------------------- dtype detect + zero (fused)

// Genuine int64 indices are all < NN; int32 data reinterpreted as int64 gives
// huge values almost surely. Sampled slots stay inside the buffer under either
// dtype (int32 buffer = 3.2M int64 slots; max sample 62812).
__global__ void k_zero(const void* __restrict__ eiraw) {
    int i = blockIdx.x * 256 + threadIdx.x;
    if (i < NN) { g_cnt_src[i] = 0; g_cnt_dst[i] = 0; g_fill[i] = 0; }
    if (i == 0) {
        g_cursor = 0u;
        const long long* p = (const long long*)eiraw;
        int ok = 1;
        for (int k = 0; k < 64; k++) {
            long long v = p[k * 997 + 1];
            if (v < 0 || v >= NN) { ok = 0; break; }
        }
        g_is64 = ok;
    }
}

__device__ __forceinline__ void decode_edge(const void* eiraw, int e, int& s, int& d) {
    if (g_is64) {
        const long long* p = (const long long*)eiraw;
        s = (int)p[e];
        d = (int)p[EE + e];
    } else {
        const int* p = (const int*)eiraw;
        s = p[e];
        d = p[EE + e];
    }
}

// ---------------------------------------------------------------- CSR build

__global__ void k_count(const void* __restrict__ eiraw) {
    int e = blockIdx.x * 256 + threadIdx.x;
    if (e >= EE) return;
    int s, d;
    decode_edge(eiraw, e, s, d);
    if ((unsigned)s >= NN || (unsigned)d >= NN) return;
    atomicAdd(&g_cnt_src[s], 1);
    atomicAdd(&g_cnt_dst[d], 1);
}

// dinv + contiguous row allocation (placement order irrelevant)
__global__ void k_dinv_rowalloc() {
    int i = blockIdx.x * 256 + threadIdx.x;
    if (i >= NN) return;
    int c = g_cnt_src[i];
    g_dinv[i] = (c > 0) ? rsqrtf((float)c) : 0.0f;
    g_rowptr[i] = (int)atomicAdd(&g_cursor, (unsigned)g_cnt_dst[i]);
}

// k_fill (blocks [0, NB_E)) fused with k_input (blocks [NB_E, NB_E+NB_4)):
// independent work, overlapped in one launch.
__global__ void __launch_bounds__(256) k_fill_input(const void* __restrict__ eiraw,
                                                    const float* __restrict__ x,
                                                    const float* __restrict__ W0,
                                                    const float* __restrict__ b0,
                                                    int nbE) {
    if (blockIdx.x < (unsigned)nbE) {
        int e = blockIdx.x * 256 + threadIdx.x;
        if (e >= EE) return;
        int s, d;
        decode_edge(eiraw, e, s, d);
        if ((unsigned)s >= NN || (unsigned)d >= NN) return;
        float w = -g_dinv[s] * g_dinv[d];
        int pos = g_rowptr[d] + atomicAdd(&g_fill[d], 1);
        g_pairs[pos] = make_int2(s, __float_as_int(w));
    } else {
        // h = relu(x @ W0 + b0). 4 lanes per node, lane handles 8 features.
        int tid = (blockIdx.x - nbE) * 256 + threadIdx.x;
        int n = tid >> 2, c = tid & 3;
        if (n >= NN) return;
        int c2 = c * 2;
        float x0 = __ldg(&x[n * 3 + 0]);
        float x1 = __ldg(&x[n * 3 + 1]);
        float x2 = __ldg(&x[n * 3 + 2]);
        const float4* W04 = (const float4*)W0;
        float4 a0 = __ldg(&((const float4*)b0)[c2]);
        float4 a1 = __ldg(&((const float4*)b0)[c2 + 1]);
#pragma unroll
        for (int r = 0; r < 3; r++) {
            float xr = r == 0 ? x0 : r == 1 ? x1 : x2;
            float4 w0 = __ldg(&W04[r * 8 + c2]);
            float4 w1 = __ldg(&W04[r * 8 + c2 + 1]);
            a0.x = fmaf(xr, w0.x, a0.x); a0.y = fmaf(xr, w0.y, a0.y);
            a0.z = fmaf(xr, w0.z, a0.z); a0.w = fmaf(xr, w0.w, a0.w);
            a1.x = fmaf(xr, w1.x, a1.x); a1.y = fmaf(xr, w1.y, a1.y);
            a1.z = fmaf(xr, w1.z, a1.z); a1.w = fmaf(xr, w1.w, a1.w);
        }
        a0.x = fmaxf(a0.x, 0.f); a0.y = fmaxf(a0.y, 0.f);
        a0.z = fmaxf(a0.z, 0.f); a0.w = fmaxf(a0.w, 0.f);
        a1.x = fmaxf(a1.x, 0.f); a1.y = fmaxf(a1.y, 0.f);
        a1.z = fmaxf(a1.z, 0.f); a1.w = fmaxf(a1.w, 0.f);
        g_hh[n * 4 + c] = pack_h8(a0, a1);
    }
}

// ---------------------------------------------------------------- propagation

// Row accumulation from fp16 features: 4 lanes per node, lane loads 16B
// (8 features); a warp covers 8 nodes -> 8 edges per warp gather-LDG.
__device__ __forceinline__ void prop_row8h(const uint4* __restrict__ Xh,
                                           int row, int deg, int c,
                                           float4& a0, float4& a1) {
    a0 = make_float4(0.f, 0.f, 0.f, 0.f);
    a1 = make_float4(0.f, 0.f, 0.f, 0.f);
#pragma unroll 8
    for (int k = 0; k < deg; k++) {
        int2 pr = __ldg(&g_pairs[row + k]);     // uniform within 4-lane group
        float w  = __int_as_float(pr.y);
        uint4 u  = __ldg(&Xh[pr.x * 4 + c]);    // 16B per lane, 64B per row
        float2 f0 = __half22float2(*reinterpret_cast<__half2*>(&u.x));
        float2 f1 = __half22float2(*reinterpret_cast<__half2*>(&u.y));
        float2 f2 = __half22float2(*reinterpret_cast<__half2*>(&u.z));
        float2 f3 = __half22float2(*reinterpret_cast<__half2*>(&u.w));
        a0.x = fmaf(w, f0.x, a0.x); a0.y = fmaf(w, f0.y, a0.y);
        a0.z = fmaf(w, f1.x, a0.z); a0.w = fmaf(w, f1.y, a0.w);
        a1.x = fmaf(w, f2.x, a1.x); a1.y = fmaf(w, f2.y, a1.y);
        a1.z = fmaf(w, f3.x, a1.z); a1.w = fmaf(w, f3.y, a1.w);
    }
}

// T1 = L~ X : gather Xh, write fp16 T1
__global__ void __launch_bounds__(256) k_prop_csr(const uint4* __restrict__ Xh) {
    int tid = blockIdx.x * 256 + threadIdx.x;
    int n = tid >> 2, c = tid & 3;
    if (n >= NN) return;
    int row = __ldg(&g_rowptr[n]);
    int deg = __ldg(&g_cnt_dst[n]);
    float4 a0, a1;
    prop_row8h(Xh, row, deg, c, a0, a1);
    g_t1h[n * 4 + c] = pack_h8(a0, a1);
}

__device__ __forceinline__ float getc8(const float4& a, const float4& b, int comp) {
    switch (comp) {
        case 0: return a.x; case 1: return a.y; case 2: return a.z; case 3: return a.w;
        case 4: return b.x; case 5: return b.y; case 6: return b.z; default: return b.w;
    }
}

// Second propagation fused with combine:
// y = L~ T1 (gathers T1h) ; T2 = 2y - X ; out = X@W[0]+T1@W[1]+T2@W[2]+b [+res][relu]
// Width-4 shfl broadcasts serve all 8 node-groups of the warp at once.
// res/out may alias Xh or each other: each thread only touches index n*4+c.
__global__ void __launch_bounds__(256) k_prop_combine(const uint4* __restrict__ Xh,
                                                      const float* __restrict__ W,
                                                      const float* __restrict__ bias,
                                                      const uint4* __restrict__ res,
                                                      uint4* __restrict__ outh) {
    __shared__ float4 sW[768];   // [3][32][8] float4 view of W[3][32][32]
    __shared__ float4 sB[8];
    for (int i = threadIdx.x; i < 768; i += 256) sW[i] = ((const float4*)W)[i];
    if (threadIdx.x < 8) sB[threadIdx.x] = ((const float4*)bias)[threadIdx.x];
    __syncthreads();

    int tid = blockIdx.x * 256 + threadIdx.x;
    int n = tid >> 2, c = tid & 3;
    if (n >= NN) return;
    int c2 = c * 2;
    int row = __ldg(&g_rowptr[n]);
    int deg = __ldg(&g_cnt_dst[n]);

    float4 xv0, xv1, t1v0, t1v1;
    unpack_h8(__ldg(&Xh[n * 4 + c]),   xv0,  xv1);
    unpack_h8(__ldg(&g_t1h[n * 4 + c]), t1v0, t1v1);
    float4 y0, y1;
    prop_row8h(g_t1h, row, deg, c, y0, y1);
    float4 t2v0 = make_float4(2.f * y0.x - xv0.x, 2.f * y0.y - xv0.y,
                              2.f * y0.z - xv0.z, 2.f * y0.w - xv0.w);
    float4 t2v1 = make_float4(2.f * y1.x - xv1.x, 2.f * y1.y - xv1.y,
                              2.f * y1.z - xv1.z, 2.f * y1.w - xv1.w);

    float4 a0 = sB[c2], a1 = sB[c2 + 1];
    if (res) {
        float4 r0, r1;
        unpack_h8(__ldg(&res[n * 4 + c]), r0, r1);
        a0.x += r0.x; a0.y += r0.y; a0.z += r0.z; a0.w += r0.w;
        a1.x += r1.x; a1.y += r1.y; a1.z += r1.z; a1.w += r1.w;
    }
#pragma unroll
    for (int i = 0; i < 32; i++) {
        const int src = i >> 3, comp = i & 7;           // compile-time
        float xi = __shfl_sync(0xffffffffu, getc8(xv0,  xv1,  comp), src, 4);
        float ai = __shfl_sync(0xffffffffu, getc8(t1v0, t1v1, comp), src, 4);
        float ti = __shfl_sync(0xffffffffu, getc8(t2v0, t2v1, comp), src, 4);
        float4 wx0 = sW[i * 8 + c2],       wx1 = sW[i * 8 + c2 + 1];
        float4 wa0 = sW[256 + i * 8 + c2], wa1 = sW[256 + i * 8 + c2 + 1];
        float4 wt0 = sW[512 + i * 8 + c2], wt1 = sW[512 + i * 8 + c2 + 1];
        a0.x = fmaf(xi, wx0.x, fmaf(ai, wa0.x, fmaf(ti, wt0.x, a0.x)));
        a0.y = fmaf(xi, wx0.y, fmaf(ai, wa0.y, fmaf(ti, wt0.y, a0.y)));
        a0.z = fmaf(xi, wx0.z, fmaf(ai, wa0.z, fmaf(ti, wt0.z, a0.z)));
        a0.w = fmaf(xi, wx0.w, fmaf(ai, wa0.w, fmaf(ti, wt0.w, a0.w)));
        a1.x = fmaf(xi, wx1.x, fmaf(ai, wa1.x, fmaf(ti, wt1.x, a1.x)));
        a1.y = fmaf(xi, wx1.y, fmaf(ai, wa1.y, fmaf(ti, wt1.y, a1.y)));
        a1.z = fmaf(xi, wx1.z, fmaf(ai, wa1.z, fmaf(ti, wt1.z, a1.z)));
        a1.w = fmaf(xi, wx1.w, fmaf(ai, wa1.w, fmaf(ti, wt1.w, a1.w)));
    }
    // relu (always applied in this network)
    a0.x = fmaxf(a0.x, 0.f); a0.y = fmaxf(a0.y, 0.f);
    a0.z = fmaxf(a0.z, 0.f); a0.w = fmaxf(a0.w, 0.f);
    a1.x = fmaxf(a1.x, 0.f); a1.y = fmaxf(a1.y, 0.f);
    a1.z = fmaxf(a1.z, 0.f); a1.w = fmaxf(a1.w, 0.f);
    outh[n * 4 + c] = pack_h8(a0, a1);
}

// ---------------------------------------------------------------- output head

__global__ void __launch_bounds__(256) k_final(const uint4* __restrict__ Hh,
                                               const float* __restrict__ W1,
                                               const float* __restrict__ b1,
                                               float* __restrict__ out) {
    int tid = blockIdx.x * 256 + threadIdx.x;
    int n = tid >> 2, c = tid & 3;
    if (n >= NN) return;
    int c2 = c * 2;
    float4 h0, h1;
    unpack_h8(__ldg(&Hh[n * 4 + c]), h0, h1);
    float4 w0 = __ldg(&((const float4*)W1)[c2]);
    float4 w1 = __ldg(&((const float4*)W1)[c2 + 1]);
    float v = h0.x * w0.x + h0.y * w0.y + h0.z * w0.z + h0.w * w0.w
            + h1.x * w1.x + h1.y * w1.y + h1.z * w1.z + h1.w * w1.w;
    v += __shfl_down_sync(0xffffffffu, v, 2, 4);
    v += __shfl_down_sync(0xffffffffu, v, 1, 4);
    if (c == 0) out[n] = v + __ldg(b1);
}

// ---------------------------------------------------------------- launch

extern "C" void kernel_launch(void* const* d_in, const int* in_sizes, int n_in,
                              void* d_out, int out_size) {
    // ---- resolve inputs by element count (robust to metadata ordering) ----
    int idx_x = 0, idx_ei = 1, idx_W0 = 2, idx_b1 = 13;
    int chebW[4] = {4, 6, 8, 10};
    int chebB[4] = {5, 7, 9, 11};
    int idx_b0 = 3, idx_W1 = 12;
    {
        int cw[4], ncw = 0, s32[8], ns = 0;
        int ix = -1, iei = -1, iw0 = -1, ib1 = -1;
        for (int i = 0; i < n_in; i++) {
            int s = in_sizes[i];
            if (s == 600000) ix = i;
            else if (s == 6400000) iei = i;
            else if (s == 96) iw0 = i;
            else if (s == 1) ib1 = i;
            else if (s == 3072 && ncw < 4) cw[ncw++] = i;
            else if (s == 32 && ns < 8) s32[ns++] = i;
        }
        if (ix >= 0 && iei >= 0 && iw0 >= 0 && ib1 >= 0 && ncw == 4 && ns == 6) {
            idx_x = ix; idx_ei = iei; idx_W0 = iw0; idx_b1 = ib1;
            int rem[2], nr = 0;
            for (int k = 0; k < 4; k++) chebW[k] = cw[k];
            for (int i = 0; i < 6; i++) {
                int isb = 0;
                for (int k = 0; k < 4; k++)
                    if (s32[i] == cw[k] + 1) { chebB[k] = s32[i]; isb = 1; }
                if (!isb && nr < 2) rem[nr++] = s32[i];
            }
            if (nr == 2) {
                if (rem[1] == rem[0] + 1) { idx_W1 = rem[0]; idx_b0 = rem[1]; }
                else                      { idx_b0 = rem[0]; idx_W1 = rem[1]; }
            }
        }
    }

    const float* x    = (const float*)d_in[idx_x];
    const void*  ei   = d_in[idx_ei];
    const float* W0   = (const float*)d_in[idx_W0];
    const float* b0   = (const float*)d_in[idx_b0];
    const float* cW[4], *cB[4];
    for (int k = 0; k < 4; k++) { cW[k] = (const float*)d_in[chebW[k]]; cB[k] = (const float*)d_in[chebB[k]]; }
    const float* W1   = (const float*)d_in[idx_W1];
    const float* b1   = (const float*)d_in[idx_b1];
    float*       out  = (float*)d_out;

    uint4 *phh, *pah;
    cudaGetSymbolAddress((void**)&phh, g_hh);
    cudaGetSymbolAddress((void**)&pah, g_ah);

    const int NB_N = (NN + 255) / 256;
    const int NB_E = (EE + 255) / 256;
    const int NB_4 = (NN * 4 + 255) / 256;   // 3125 blocks: 4 threads per node

    k_zero<<<NB_N, 256>>>(ei);
    k_count<<<NB_E, 256>>>(ei);
    k_dinv_rowalloc<<<NB_N, 256>>>();
    k_fill_input<<<NB_E + NB_4, 256>>>(ei, x, W0, b0, NB_E);

    auto cheb = [&](int k, const uint4* Xb, const uint4* resb, uint4* outb) {
        k_prop_csr<<<NB_4, 256>>>(Xb);
        k_prop_combine<<<NB_4, 256>>>(Xb, cW[k], cB[k], resb, outb);
    };

    // block 1: h0=h; h=relu(conv11(h)); h=relu(conv12(h)+h0)
    cheb(0, phh, nullptr, pah);
    cheb(1, pah, phh,     phh);
    // block 2
    cheb(2, phh, nullptr, pah);
    cheb(3, pah, phh,     phh);

    k_final<<<NB_4, 256>>>(phh, W1, b1, out);
}